// round 8
// baseline (speedup 1.0000x reference)
#include <cuda_runtime.h>

// Problem constants (fixed by the dataset)
#define NN 50000
#define EE 1600000
#define DD 64
#define HH 32
#define NEG_SLOPE 0.2f

#define PROJ_THREADS (2 * NN)                     // 2 threads per node (half-split)
#define PROJ_BLOCKS ((PROJ_THREADS + 255) / 256)  // 391
#define HIST_BLOCKS ((EE + 255) / 256)            // 6250

// ---------------- scratch (static device globals; no allocation allowed) ----
__device__ float d_xl[NN * HH];
__device__ float d_xr[NN * HH];
__device__ float d_hbuf[NN * HH];
__device__ int d_deg[NN];
__device__ int d_rowoff[NN + 1];
__device__ int d_cursor[NN];
__device__ int d_esrc[EE];

// ---------------- proj body (half-split: 2 threads per node) ----------------
template <int DIN>
__device__ __forceinline__ void proj_body(int blockId, int tid,
                                          const float* __restrict__ x,
                                          const float* __restrict__ Wl,
                                          const float* __restrict__ Wr,
                                          float* __restrict__ xl,
                                          float* __restrict__ xr) {
    __shared__ float2 sWl[DIN * 16];
    __shared__ float2 sWr[DIN * 16];
    for (int t = tid; t < DIN * 16; t += 256) {
        sWl[t] = ((const float2*)Wl)[t];
        sWr[t] = ((const float2*)Wr)[t];
    }
    __syncthreads();
    int gid = blockId * 256 + tid;
    int node = gid >> 1;
    int half = gid & 1;
    if (node >= NN) return;

    float2 al[8], ar[8];
#pragma unroll
    for (int c = 0; c < 8; c++) {
        al[c] = make_float2(0.f, 0.f);
        ar[c] = make_float2(0.f, 0.f);
    }
    const float4* xrow = (const float4*)(x + (size_t)node * DIN);
#pragma unroll 4
    for (int k4 = 0; k4 < DIN / 4; k4++) {
        float4 xv = xrow[k4];
        float xs[4] = {xv.x, xv.y, xv.z, xv.w};
#pragma unroll
        for (int q = 0; q < 4; q++) {
            int k = k4 * 4 + q;
            float xk = xs[q];
            int wbase = k * 16 + half * 8;
#pragma unroll
            for (int c = 0; c < 8; c++) {
                float2 w = sWl[wbase + c];
                al[c].x += xk * w.x;
                al[c].y += xk * w.y;
                float2 w2 = sWr[wbase + c];
                ar[c].x += xk * w2.x;
                ar[c].y += xk * w2.y;
            }
        }
    }
    float2* ol = (float2*)(xl + (size_t)node * HH + half * 16);
    float2* orr = (float2*)(xr + (size_t)node * HH + half * 16);
#pragma unroll
    for (int c = 0; c < 8; c++) {
        ol[c] = al[c];
        orr[c] = ar[c];
    }
}

// ---------------- fused: proj64 (layer1) + degree histogram ----------------
__global__ void proj64_hist_kernel(const float* __restrict__ x,
                                   const float* __restrict__ Wl,
                                   const float* __restrict__ Wr,
                                   float* __restrict__ xl, float* __restrict__ xr,
                                   const int* __restrict__ dst) {
    if (blockIdx.x < PROJ_BLOCKS) {
        proj_body<DD>(blockIdx.x, threadIdx.x, x, Wl, Wr, xl, xr);
    } else {
        int e = (blockIdx.x - PROJ_BLOCKS) * 256 + threadIdx.x;
        if (e < EE) atomicAdd(&d_deg[dst[e]], 1);
    }
}

__global__ void proj32_kernel(const float* __restrict__ x,
                              const float* __restrict__ Wl,
                              const float* __restrict__ Wr,
                              float* __restrict__ xl, float* __restrict__ xr) {
    proj_body<HH>(blockIdx.x, threadIdx.x, x, Wl, Wr, xl, xr);
}

// ---------------- CSR: fused single-block scan ----------------
__global__ void scan_fused_kernel() {
    __shared__ int wsum[32];
    const int CH = 49;  // 1024 * 49 >= NN
    int t = threadIdx.x;
    int lane = t & 31, wid = t >> 5;
    int base = t * CH;
    int sum = 0;
#pragma unroll 7
    for (int k = 0; k < CH; k++) {
        int i = base + k;
        if (i < NN) sum += d_deg[i];
    }
    int x = sum;
#pragma unroll
    for (int o = 1; o < 32; o <<= 1) {
        int y = __shfl_up_sync(0xffffffffu, x, o);
        if (lane >= o) x += y;
    }
    if (lane == 31) wsum[wid] = x;
    __syncthreads();
    if (wid == 0) {
        int w = wsum[lane];
#pragma unroll
        for (int o = 1; o < 32; o <<= 1) {
            int y = __shfl_up_sync(0xffffffffu, w, o);
            if (lane >= o) w += y;
        }
        wsum[lane] = w;
    }
    __syncthreads();
    int pref = (x - sum) + ((wid > 0) ? wsum[wid - 1] : 0);
    int run = pref;
#pragma unroll 7
    for (int k = 0; k < CH; k++) {
        int i = base + k;
        if (i < NN) {
            int d = d_deg[i];
            d_rowoff[i] = run;
            d_cursor[i] = run;
            run += d;
        }
    }
    if (t == 0) d_rowoff[NN] = EE;
}

__global__ void scatter_kernel(const int* __restrict__ src, const int* __restrict__ dst) {
    int e = blockIdx.x * blockDim.x + threadIdx.x;
    if (e < EE) {
        int p = atomicAdd(&d_cursor[dst[e]], 1);
        d_esrc[p] = src[e];
    }
}

// ---------------- GATv2 edge layer: XOR-skewed transpose-reduce -------------
// Warp per node, lane = channel. Lane l processes sub-tile edges in XOR-skewed
// order (v[j] = edge j ^ (l&15)), which makes every merge of the reduce tree
// the UNIFORM  d[m] = a[2m] + shfl_xor(a[2m+1], o)  -- no keep/send selects
// (saves 2 FSELs x 15 merges per 16 edges). After 4 stages lane l holds edge
// (l&15)'s logit (same position as unskewed); one o=16 both-add closes the
// channel dim. p-broadcast for accumulation is shfl_xor(p, m): lane l receives
// edge (l&15)^m == v[m]'s edge. Gather uses s_lo/s_hi (slot low-4-bits
// duplicated across halves, built once per 32-slot tile) so shfl_xor(s, j)
// with an immediate mask yields slot 16h + ((l&15)^j) identically in both
// halves. ONE exp per 16 edges; shift-invariant softmax (p = exp(e-8)).
__global__ void gat_kernel(const float* __restrict__ xl,
                           const float* __restrict__ xr,
                           const float* __restrict__ att,
                           const float* __restrict__ bias,
                           float* __restrict__ out, int do_relu) {
    int node = (blockIdx.x * blockDim.x + threadIdx.x) >> 5;
    if (node >= NN) return;
    int lane = threadIdx.x & 31;
    int lx = lane & 15;

    float att_c = att[lane];
    float a06 = 0.6f * att_c;
    float a04 = 0.4f * att_c;
    float xr_c = xr[node * HH + lane];
    int row = d_rowoff[node];
    int end = d_rowoff[node + 1];

    float den_l = 0.f, acc = 0.f;

    for (int base = row; base < end; base += 32) {
        int idx = base + lane;
        int s_raw = d_esrc[(idx < end) ? idx : (end - 1)];
        // duplicate slot groups across halves: lane l holds slot (l&15) / 16+(l&15)
        int s_lo = __shfl_sync(0xffffffffu, s_raw, lx);
        int s_hi = __shfl_sync(0xffffffffu, s_raw, lx | 16);

#pragma unroll
        for (int h = 0; h < 2; h++) {
            int sb = base + 16 * h;
            if (sb >= end) break;
            int s_sub = h ? s_hi : s_lo;

            // skewed gather: v[j] = edge (j ^ lx) of this sub-tile
            float v[16];
#pragma unroll
            for (int j = 0; j < 16; j++) {
                int sj = __shfl_xor_sync(0xffffffffu, s_sub, j);
                v[j] = __ldg(&xl[sj * HH + lane]);
            }

            // stage 1 (o=1) fused with logit; select-free merges throughout
            float d8[8];
#pragma unroll
            for (int m = 0; m < 8; m++) {
                float t0 = v[2 * m] + xr_c;
                float c0 = fmaf(a04, fabsf(t0), a06 * t0);
                float t1 = v[2 * m + 1] + xr_c;
                float c1 = fmaf(a04, fabsf(t1), a06 * t1);
                d8[m] = c0 + __shfl_xor_sync(0xffffffffu, c1, 1);
            }
            float d4[4];
#pragma unroll
            for (int m = 0; m < 4; m++)
                d4[m] = d8[2 * m] + __shfl_xor_sync(0xffffffffu, d8[2 * m + 1], 2);
            float d2[2];
#pragma unroll
            for (int m = 0; m < 2; m++)
                d2[m] = d4[2 * m] + __shfl_xor_sync(0xffffffffu, d4[2 * m + 1], 4);
            float d1 = d2[0] + __shfl_xor_sync(0xffffffffu, d2[1], 8);
            // close channel bit 4: lane l now holds full logit of edge (l&15)
            float e = d1 + __shfl_xor_sync(0xffffffffu, d1, 16);

            // one exp per 16 edges; mask invalid slots
            bool valid = (sb + lx) < end;
            float p = valid ? __expf(e - 8.f) : 0.f;
            den_l += p;  // duplicated across half-warps; halved at the end

            // accumulate: shfl_xor(p, m) delivers edge (lx^m) == v[m]'s edge
#pragma unroll
            for (int j = 0; j < 16; j++) {
                float pj = __shfl_xor_sync(0xffffffffu, p, j);
                acc += pj * v[j];
            }
        }
    }

    // total denom = (sum over all 32 lanes of den_l) / 2  (duplication)
    float den = den_l;
#pragma unroll
    for (int o = 16; o; o >>= 1) den += __shfl_xor_sync(0xffffffffu, den, o);
    den *= 0.5f;

    float res;
    if (end > row)
        res = acc / den + bias[lane];
    else
        res = bias[lane];
    if (do_relu) res = fmaxf(res, 0.f);
    out[node * HH + lane] = res;
}

// ---------------- launch ----------------
extern "C" void kernel_launch(void* const* d_in, const int* in_sizes, int n_in,
                              void* d_out, int out_size) {
    const float* x = (const float*)d_in[0];
    const int* ei = (const int*)d_in[1];
    const float* Wl1 = (const float*)d_in[2];
    const float* Wr1 = (const float*)d_in[3];
    const float* att1 = (const float*)d_in[4];
    const float* b1 = (const float*)d_in[5];
    const float* Wl2 = (const float*)d_in[6];
    const float* Wr2 = (const float*)d_in[7];
    const float* att2 = (const float*)d_in[8];
    const float* b2 = (const float*)d_in[9];
    float* out = (float*)d_out;

    const int* src = ei;
    const int* dst = ei + EE;

    float* xl;
    float* xr;
    float* hbuf;
    int* deg;
    cudaGetSymbolAddress((void**)&xl, d_xl);
    cudaGetSymbolAddress((void**)&xr, d_xr);
    cudaGetSymbolAddress((void**)&hbuf, d_hbuf);
    cudaGetSymbolAddress((void**)&deg, d_deg);

    cudaMemsetAsync(deg, 0, NN * sizeof(int));

    // fused layer-1 projection + degree histogram
    proj64_hist_kernel<<<PROJ_BLOCKS + HIST_BLOCKS, 256>>>(x, Wl1, Wr1, xl, xr, dst);
    // prefix scan
    scan_fused_kernel<<<1, 1024>>>();
    // CSR scatter
    scatter_kernel<<<HIST_BLOCKS, 256>>>(src, dst);
    // gat layer 1
    gat_kernel<<<(NN + 7) / 8, 256>>>(xl, xr, att1, b1, hbuf, 1);
    // layer-2 projection
    proj32_kernel<<<PROJ_BLOCKS, 256>>>(hbuf, Wl2, Wr2, xl, xr);
    // gat layer 2
    gat_kernel<<<(NN + 7) / 8, 256>>>(xl, xr, att2, b2, out, 0);
}

// round 11
// speedup vs baseline: 1.2310x; 1.2310x over previous
#include <cuda_runtime.h>

// Problem constants (fixed by the dataset)
#define NN 50000
#define EE 1600000
#define DD 64
#define HH 32
#define NEG_SLOPE 0.2f

#define PROJ_THREADS (2 * NN)                     // 2 threads per node (half-split)
#define PROJ_BLOCKS ((PROJ_THREADS + 255) / 256)  // 391
#define HIST_BLOCKS ((EE + 255) / 256)            // 6250
#define GAT_BLOCKS (NN / 16)                      // 2 nodes/warp, 8 warps/block

// ---------------- scratch (static device globals; no allocation allowed) ----
__device__ float d_xl[NN * HH];
__device__ float d_xr[NN * HH];
__device__ float d_hbuf[NN * HH];
__device__ int d_deg[NN];
__device__ int d_rowoff[NN + 1];
__device__ int d_cursor[NN];
__device__ int d_esrc[EE];

// ---------------- proj body (half-split: 2 threads per node) ----------------
template <int DIN>
__device__ __forceinline__ void proj_body(int blockId, int tid,
                                          const float* __restrict__ x,
                                          const float* __restrict__ Wl,
                                          const float* __restrict__ Wr,
                                          float* __restrict__ xl,
                                          float* __restrict__ xr) {
    __shared__ float2 sWl[DIN * 16];
    __shared__ float2 sWr[DIN * 16];
    for (int t = tid; t < DIN * 16; t += 256) {
        sWl[t] = ((const float2*)Wl)[t];
        sWr[t] = ((const float2*)Wr)[t];
    }
    __syncthreads();
    int gid = blockId * 256 + tid;
    int node = gid >> 1;
    int half = gid & 1;
    if (node >= NN) return;

    float2 al[8], ar[8];
#pragma unroll
    for (int c = 0; c < 8; c++) {
        al[c] = make_float2(0.f, 0.f);
        ar[c] = make_float2(0.f, 0.f);
    }
    const float4* xrow = (const float4*)(x + (size_t)node * DIN);
#pragma unroll 4
    for (int k4 = 0; k4 < DIN / 4; k4++) {
        float4 xv = xrow[k4];
        float xs[4] = {xv.x, xv.y, xv.z, xv.w};
#pragma unroll
        for (int q = 0; q < 4; q++) {
            int k = k4 * 4 + q;
            float xk = xs[q];
            int wbase = k * 16 + half * 8;
#pragma unroll
            for (int c = 0; c < 8; c++) {
                float2 w = sWl[wbase + c];
                al[c].x += xk * w.x;
                al[c].y += xk * w.y;
                float2 w2 = sWr[wbase + c];
                ar[c].x += xk * w2.x;
                ar[c].y += xk * w2.y;
            }
        }
    }
    float2* ol = (float2*)(xl + (size_t)node * HH + half * 16);
    float2* orr = (float2*)(xr + (size_t)node * HH + half * 16);
#pragma unroll
    for (int c = 0; c < 8; c++) {
        ol[c] = al[c];
        orr[c] = ar[c];
    }
}

// ---------------- fused: proj64 (layer1) + degree histogram ----------------
__global__ void proj64_hist_kernel(const float* __restrict__ x,
                                   const float* __restrict__ Wl,
                                   const float* __restrict__ Wr,
                                   float* __restrict__ xl, float* __restrict__ xr,
                                   const int* __restrict__ dst) {
    if (blockIdx.x < PROJ_BLOCKS) {
        proj_body<DD>(blockIdx.x, threadIdx.x, x, Wl, Wr, xl, xr);
    } else {
        int e = (blockIdx.x - PROJ_BLOCKS) * 256 + threadIdx.x;
        if (e < EE) atomicAdd(&d_deg[dst[e]], 1);
    }
}

__global__ void proj32_kernel(const float* __restrict__ x,
                              const float* __restrict__ Wl,
                              const float* __restrict__ Wr,
                              float* __restrict__ xl, float* __restrict__ xr) {
    proj_body<HH>(blockIdx.x, threadIdx.x, x, Wl, Wr, xl, xr);
}

// ---------------- CSR: fused single-block scan ----------------
__global__ void scan_fused_kernel() {
    __shared__ int wsum[32];
    const int CH = 49;  // 1024 * 49 >= NN
    int t = threadIdx.x;
    int lane = t & 31, wid = t >> 5;
    int base = t * CH;
    int sum = 0;
#pragma unroll 7
    for (int k = 0; k < CH; k++) {
        int i = base + k;
        if (i < NN) sum += d_deg[i];
    }
    int x = sum;
#pragma unroll
    for (int o = 1; o < 32; o <<= 1) {
        int y = __shfl_up_sync(0xffffffffu, x, o);
        if (lane >= o) x += y;
    }
    if (lane == 31) wsum[wid] = x;
    __syncthreads();
    if (wid == 0) {
        int w = wsum[lane];
#pragma unroll
        for (int o = 1; o < 32; o <<= 1) {
            int y = __shfl_up_sync(0xffffffffu, w, o);
            if (lane >= o) w += y;
        }
        wsum[lane] = w;
    }
    __syncthreads();
    int pref = (x - sum) + ((wid > 0) ? wsum[wid - 1] : 0);
    int run = pref;
#pragma unroll 7
    for (int k = 0; k < CH; k++) {
        int i = base + k;
        if (i < NN) {
            int d = d_deg[i];
            d_rowoff[i] = run;
            d_cursor[i] = run;
            run += d;
        }
    }
    if (t == 0) d_rowoff[NN] = EE;
}

__global__ void scatter_kernel(const int* __restrict__ src, const int* __restrict__ dst) {
    int e = blockIdx.x * blockDim.x + threadIdx.x;
    if (e < EE) {
        int p = atomicAdd(&d_cursor[dst[e]], 1);
        d_esrc[p] = src[e];
    }
}

// ---------------- GATv2 edge layer: 2 nodes/warp, float2 channels -----------
// Half-warp per node; lane q=lane&15 owns channel pair (2q, 2q+1). Every
// instruction in the tile loop serves BOTH nodes. Per 8-edge sub-tile (x2
// nodes = 16 edges):
//   - 8 broadcast gathers (16 lanes x float2 = one 128B row per half-warp)
//   - logit split: att.lrelu(v+xr) = 0.6 att.v + 0.4 att.|v+xr| + K, with
//     per-node K = 0.6 att.xr folded into the exp shift (Koff = K - 8)
//   - 3 halving stages (bits 0-2 of q) + one both-add at xor 8: lane q ends
//     with full logit of edge (q&7) of its half's node
//   - ONE exp per 16 edges; invalid slots masked to p=0 (no remainder loop)
//   - den summed over 16 lanes counts each edge twice -> 2/den at the end
__global__ void __launch_bounds__(256) gat_kernel(
    const float* __restrict__ xl, const float* __restrict__ xr,
    const float* __restrict__ att, const float* __restrict__ bias,
    float* __restrict__ out, int do_relu) {
    int warpId = (blockIdx.x * blockDim.x + threadIdx.x) >> 5;
    if (warpId * 2 >= NN) return;  // uniform per warp (NN even)
    int lane = threadIdx.x & 31;
    int q = lane & 15;
    int hb = lane & 16;
    int node = warpId * 2 + (lane >> 4);

    float2 att2 = ((const float2*)att)[q];
    float2 a06 = make_float2(0.6f * att2.x, 0.6f * att2.y);
    float2 a04 = make_float2(0.4f * att2.x, 0.4f * att2.y);
    float2 xr2 = ((const float2*)(xr + node * HH))[q];
    float2 b2v = ((const float2*)bias)[q];
    int row = d_rowoff[node];
    int end = d_rowoff[node + 1];
    int deg = end - row;
    int md = max(deg, __shfl_xor_sync(0xffffffffu, deg, 16));

    // per-node constant K = 0.6 * att.xr, folded into exp shift
    float kp = a06.x * xr2.x + a06.y * xr2.y;
    kp += __shfl_xor_sync(0xffffffffu, kp, 1);
    kp += __shfl_xor_sync(0xffffffffu, kp, 2);
    kp += __shfl_xor_sync(0xffffffffu, kp, 4);
    kp += __shfl_xor_sync(0xffffffffu, kp, 8);
    float Koff = kp - 8.f;

    float den = 0.f;
    float2 acc = make_float2(0.f, 0.f);
    int q7 = q & 7;

    for (int off = 0; off < md; off += 16) {
        int idx = row + off + q;
        int sidx = (deg > 0) ? min(idx, end - 1) : 0;
        int s_l = d_esrc[sidx];

#pragma unroll
        for (int t = 0; t < 2; t++) {
            if (off + 8 * t >= md) break;  // uniform (md warp-uniform)

            float2 v[8];
#pragma unroll
            for (int j = 0; j < 8; j++) {
                int sj = __shfl_sync(0xffffffffu, s_l, hb + 8 * t + j);
                v[j] = __ldg(&((const float2*)(xl + sj * HH))[q]);
            }

            // logit contributions fused with stage 1 (bit 0)
            float d4[4];
#pragma unroll
            for (int m = 0; m < 4; m++) {
                float2 va = v[2 * m], vb = v[2 * m + 1];
                float tax = va.x + xr2.x, tay = va.y + xr2.y;
                float c0 = fmaf(a04.y, fabsf(tay),
                                fmaf(a04.x, fabsf(tax),
                                     fmaf(a06.y, va.y, a06.x * va.x)));
                float tbx = vb.x + xr2.x, tby = vb.y + xr2.y;
                float c1 = fmaf(a04.y, fabsf(tby),
                                fmaf(a04.x, fabsf(tbx),
                                     fmaf(a06.y, vb.y, a06.x * vb.x)));
                float keep = (q & 1) ? c1 : c0;
                float send = (q & 1) ? c0 : c1;
                d4[m] = keep + __shfl_xor_sync(0xffffffffu, send, 1);
            }
            // stage 2 (bit 1)
            float d2[2];
#pragma unroll
            for (int m = 0; m < 2; m++) {
                float keep = (q & 2) ? d4[2 * m + 1] : d4[2 * m];
                float send = (q & 2) ? d4[2 * m] : d4[2 * m + 1];
                d2[m] = keep + __shfl_xor_sync(0xffffffffu, send, 2);
            }
            // stage 3 (bit 2)
            float keep = (q & 4) ? d2[1] : d2[0];
            float send = (q & 4) ? d2[0] : d2[1];
            float d1 = keep + __shfl_xor_sync(0xffffffffu, send, 4);
            // close remaining lane bit 3: lane q holds edge (q&7)'s full logit
            float e = d1 + __shfl_xor_sync(0xffffffffu, d1, 8);

            bool valid = (off + 8 * t + q7) < deg;
            float p = valid ? __expf(e + Koff) : 0.f;
            den += p;

#pragma unroll
            for (int j = 0; j < 8; j++) {
                float pj = __shfl_sync(0xffffffffu, p, hb + j);
                acc.x = fmaf(pj, v[j].x, acc.x);
                acc.y = fmaf(pj, v[j].y, acc.y);
            }
        }
    }

    // den over 16 lanes counts each edge twice
    den += __shfl_xor_sync(0xffffffffu, den, 1);
    den += __shfl_xor_sync(0xffffffffu, den, 2);
    den += __shfl_xor_sync(0xffffffffu, den, 4);
    den += __shfl_xor_sync(0xffffffffu, den, 8);

    float2 res;
    if (deg > 0) {
        float inv = 2.f / den;
        res.x = fmaf(acc.x, inv, b2v.x);
        res.y = fmaf(acc.y, inv, b2v.y);
    } else {
        res = b2v;
    }
    if (do_relu) {
        res.x = fmaxf(res.x, 0.f);
        res.y = fmaxf(res.y, 0.f);
    }
    ((float2*)(out + node * HH))[q] = res;
}

// ---------------- launch ----------------
extern "C" void kernel_launch(void* const* d_in, const int* in_sizes, int n_in,
                              void* d_out, int out_size) {
    const float* x = (const float*)d_in[0];
    const int* ei = (const int*)d_in[1];
    const float* Wl1 = (const float*)d_in[2];
    const float* Wr1 = (const float*)d_in[3];
    const float* att1 = (const float*)d_in[4];
    const float* b1 = (const float*)d_in[5];
    const float* Wl2 = (const float*)d_in[6];
    const float* Wr2 = (const float*)d_in[7];
    const float* att2 = (const float*)d_in[8];
    const float* b2 = (const float*)d_in[9];
    float* out = (float*)d_out;

    const int* src = ei;
    const int* dst = ei + EE;

    float* xl;
    float* xr;
    float* hbuf;
    int* deg;
    cudaGetSymbolAddress((void**)&xl, d_xl);
    cudaGetSymbolAddress((void**)&xr, d_xr);
    cudaGetSymbolAddress((void**)&hbuf, d_hbuf);
    cudaGetSymbolAddress((void**)&deg, d_deg);

    cudaMemsetAsync(deg, 0, NN * sizeof(int));

    // fused layer-1 projection + degree histogram
    proj64_hist_kernel<<<PROJ_BLOCKS + HIST_BLOCKS, 256>>>(x, Wl1, Wr1, xl, xr, dst);
    // prefix scan
    scan_fused_kernel<<<1, 1024>>>();
    // CSR scatter
    scatter_kernel<<<HIST_BLOCKS, 256>>>(src, dst);
    // gat layer 1
    gat_kernel<<<GAT_BLOCKS, 256>>>(xl, xr, att1, b1, hbuf, 1);
    // layer-2 projection
    proj32_kernel<<<PROJ_BLOCKS, 256>>>(hbuf, Wl2, Wr2, xl, xr);
    // gat layer 2
    gat_kernel<<<GAT_BLOCKS, 256>>>(xl, xr, att2, b2, out, 0);
}